// round 1
// baseline (speedup 1.0000x reference)
#include <cuda_runtime.h>

#define RR 8
#define BB 8
#define LL 2048
#define PP 16384
#define HQ 32
#define HKV 8
#define GG 4
#define DD 128
#define NSPLIT 8
#define CHUNK (LL / NSPLIT)   // 256
#define TILE 64
#define SCALE_F 0.08838834764831845f
#define NEGINF -1.0e30f
#define HD (HKV * DD)         // 1024 floats per page row

// Scratch for split-KV partials (device globals; no runtime allocation).
__device__ float g_po[RR * NSPLIT * BB * HQ * DD];   // normalized partial O
__device__ float g_plse[RR * NSPLIT * BB * HQ];      // partial LSE

__global__ void __launch_bounds__(128)
decode_kernel(const float* __restrict__ q,
              const float* __restrict__ kc,
              const float* __restrict__ vc,
              const int* __restrict__ lens,
              const int* __restrict__ bt)
{
    const int split = blockIdx.x;
    const int hkv   = blockIdx.y;
    const int rb    = blockIdx.z;          // r*BB + b
    const int r     = rb >> 3;
    const int b     = rb & 7;
    const int tid   = threadIdx.x;
    const int wid   = tid >> 5;            // 0..3  (warp == head)
    const int lane  = tid & 31;
    const int half  = lane >> 4;           // half-warp -> token
    const int hl    = lane & 15;           // lane within half

    const int kv_len = lens[rb];
    const int start  = split * CHUNK;
    const int end    = min(start + CHUNK, kv_len);
    const int pbase  = ((r * NSPLIT + split) * BB + b) * HQ + hkv * GG;

    if (end <= start) {
        // Empty split: zero partial so the combine's 0-weight (or all-empty) path is exact.
        #pragma unroll
        for (int g = 0; g < GG; ++g)
            g_po[(pbase + g) * DD + tid] = 0.0f;
        if (tid < GG)
            g_plse[pbase + tid] = NEGINF;
        return;
    }

    __shared__ float4 s_s[TILE];   // scores  [token][4 heads]
    __shared__ float4 p_s[TILE];   // probs   [token][4 heads]
    __shared__ int    pg_s[TILE];  // page per token
    __shared__ float  m_s[GG], sc_s[GG], l_s[GG];

    if (tid < GG) { m_s[tid] = NEGINF; l_s[tid] = 0.0f; }

    // Q into registers: head g, dims hl*8 .. hl*8+7
    const float* qb = q + (b * HQ + hkv * GG) * DD + hl * 8;
    float4 q0[GG], q1[GG];
    #pragma unroll
    for (int g = 0; g < GG; ++g) {
        q0[g] = *(const float4*)(qb + g * DD);
        q1[g] = *(const float4*)(qb + g * DD + 4);
    }

    const int*   btb = bt + rb * LL;
    const float* kh  = kc + (long)r * PP * HD + hkv * DD;
    const float* vh  = vc + (long)r * PP * HD + hkv * DD + tid;

    float acc0 = 0.f, acc1 = 0.f, acc2 = 0.f, acc3 = 0.f;
    __syncthreads();

    for (int tb = start; tb < end; tb += TILE) {
        const int nt = min(TILE, end - tb);

        // ---- Phase A: scores. Half-warp per token, 8 tokens/CTA per pass.
        #pragma unroll
        for (int pass = 0; pass < 8; ++pass) {
            const int  tt    = pass * 8 + wid * 2 + half;
            const bool valid = (tt < nt);
            const int  page  = valid ? __ldg(btb + tb + tt) : 0;
            const float* kt  = kh + (long)page * HD + hl * 8;
            const float4 k0  = *(const float4*)kt;
            const float4 k1  = *(const float4*)(kt + 4);

            float s0 = q0[0].x*k0.x + q0[0].y*k0.y + q0[0].z*k0.z + q0[0].w*k0.w
                     + q1[0].x*k1.x + q1[0].y*k1.y + q1[0].z*k1.z + q1[0].w*k1.w;
            float s1 = q0[1].x*k0.x + q0[1].y*k0.y + q0[1].z*k0.z + q0[1].w*k0.w
                     + q1[1].x*k1.x + q1[1].y*k1.y + q1[1].z*k1.z + q1[1].w*k1.w;
            float s2 = q0[2].x*k0.x + q0[2].y*k0.y + q0[2].z*k0.z + q0[2].w*k0.w
                     + q1[2].x*k1.x + q1[2].y*k1.y + q1[2].z*k1.z + q1[2].w*k1.w;
            float s3 = q0[3].x*k0.x + q0[3].y*k0.y + q0[3].z*k0.z + q0[3].w*k0.w
                     + q1[3].x*k1.x + q1[3].y*k1.y + q1[3].z*k1.z + q1[3].w*k1.w;

            // Reduce over the 16 lanes of this half-warp (offsets stay intra-half).
            #pragma unroll
            for (int off = 8; off; off >>= 1) {
                s0 += __shfl_xor_sync(0xffffffffu, s0, off);
                s1 += __shfl_xor_sync(0xffffffffu, s1, off);
                s2 += __shfl_xor_sync(0xffffffffu, s2, off);
                s3 += __shfl_xor_sync(0xffffffffu, s3, off);
            }
            if (hl == 0) {
                s_s[tt] = valid ? make_float4(s0 * SCALE_F, s1 * SCALE_F,
                                              s2 * SCALE_F, s3 * SCALE_F)
                                : make_float4(NEGINF, NEGINF, NEGINF, NEGINF);
                pg_s[tt] = page;
            }
        }
        __syncthreads();

        // ---- Running max per head (warp wid owns head wid).
        {
            const float* sf = (const float*)s_s;
            float x = fmaxf(sf[lane * 4 + wid], sf[(lane + 32) * 4 + wid]);
            #pragma unroll
            for (int off = 16; off; off >>= 1)
                x = fmaxf(x, __shfl_xor_sync(0xffffffffu, x, off));
            if (lane == 0) {
                const float mo = m_s[wid];
                const float mn = fmaxf(mo, x);
                sc_s[wid] = __expf(mo - mn);
                m_s[wid]  = mn;
            }
        }
        __syncthreads();

        // ---- Rescale accumulators, compute p, update l.
        {
            acc0 *= sc_s[0]; acc1 *= sc_s[1]; acc2 *= sc_s[2]; acc3 *= sc_s[3];
            const float* sf = (const float*)s_s;
            float*       pf = (float*)p_s;
            const float  m  = m_s[wid];
            const float  pa = __expf(sf[lane * 4 + wid] - m);
            const float  pb = __expf(sf[(lane + 32) * 4 + wid] - m);
            pf[lane * 4 + wid]        = pa;
            pf[(lane + 32) * 4 + wid] = pb;
            float ps = pa + pb;
            #pragma unroll
            for (int off = 16; off; off >>= 1)
                ps += __shfl_xor_sync(0xffffffffu, ps, off);
            if (lane == 0)
                l_s[wid] = l_s[wid] * sc_s[wid] + ps;
        }
        __syncthreads();

        // ---- Phase B: P·V. Thread tid owns output dim d = tid for all 4 heads.
        #pragma unroll 8
        for (int j = 0; j < nt; ++j) {
            const float4 p4 = p_s[j];
            const float  v  = __ldg(vh + (long)pg_s[j] * HD);
            acc0 += p4.x * v; acc1 += p4.y * v;
            acc2 += p4.z * v; acc3 += p4.w * v;
        }
        __syncthreads();
    }

    const float l0 = fmaxf(l_s[0], 1e-30f);
    const float l1 = fmaxf(l_s[1], 1e-30f);
    const float l2 = fmaxf(l_s[2], 1e-30f);
    const float l3 = fmaxf(l_s[3], 1e-30f);
    g_po[(pbase + 0) * DD + tid] = acc0 / l0;
    g_po[(pbase + 1) * DD + tid] = acc1 / l1;
    g_po[(pbase + 2) * DD + tid] = acc2 / l2;
    g_po[(pbase + 3) * DD + tid] = acc3 / l3;
    if (tid < GG)
        g_plse[pbase + tid] = m_s[tid] + __logf(fmaxf(l_s[tid], 1e-30f));
}

__global__ void __launch_bounds__(128)
combine_kernel(float* __restrict__ out)
{
    const int bh = blockIdx.x;    // b*HQ + hq
    const int d  = threadIdx.x;   // 0..127

    __shared__ float lse_s[RR * NSPLIT];
    if (d < RR * NSPLIT)
        lse_s[d] = g_plse[d * (BB * HQ) + bh];
    __syncthreads();

    float gm = NEGINF;
    #pragma unroll
    for (int i = 0; i < RR * NSPLIT; ++i)
        gm = fmaxf(gm, lse_s[i]);

    float acc = 0.f, ws = 0.f;
    #pragma unroll
    for (int i = 0; i < RR * NSPLIT; ++i) {
        const float w = __expf(lse_s[i] - gm);
        ws  += w;
        acc += w * g_po[(i * (BB * HQ) + bh) * DD + d];
    }
    out[bh * DD + d] = acc / ws;
}

extern "C" void kernel_launch(void* const* d_in, const int* in_sizes, int n_in,
                              void* d_out, int out_size)
{
    (void)in_sizes; (void)n_in; (void)out_size;
    const float* q    = (const float*)d_in[0];
    const float* kc   = (const float*)d_in[1];
    const float* vc   = (const float*)d_in[2];
    const int*   lens = (const int*)d_in[3];
    const int*   bt   = (const int*)d_in[4];

    dim3 grid1(NSPLIT, HKV, RR * BB);
    decode_kernel<<<grid1, 128>>>(q, kc, vc, lens, bt);
    combine_kernel<<<BB * HQ, 128>>>((float*)d_out);
}

// round 3
// speedup vs baseline: 1.1994x; 1.1994x over previous
#include <cuda_runtime.h>

#define RR 8
#define BB 8
#define LL 2048
#define PP 16384
#define HQ 32
#define HKV 8
#define GG 4
#define DD 128
#define NSPLIT 16
#define CHUNK (LL / NSPLIT)   // 128
#define TILE 64
#define RS (RR * NSPLIT)      // 128 partials per (b, hq)
#define SCALE_F 0.08838834764831845f
#define NEGINF -1.0e30f
#define HD (HKV * DD)         // 1024 floats per page row

// Scratch for split-KV partials (device globals; no runtime allocation).
__device__ float g_po[RS * BB * HQ * DD];   // normalized partial O (~16.8MB)
__device__ float g_plse[RS * BB * HQ];      // partial LSE

__global__ void __launch_bounds__(128)
decode_kernel(const float* __restrict__ q,
              const float* __restrict__ kc,
              const float* __restrict__ vc,
              const int* __restrict__ lens,
              const int* __restrict__ bt)
{
    const int split = blockIdx.x;
    const int hkv   = blockIdx.y;
    const int rb    = blockIdx.z;          // r*BB + b
    const int r     = rb >> 3;
    const int b     = rb & 7;
    const int tid   = threadIdx.x;
    const int wid   = tid >> 5;            // 0..3  (warp == head for softmax)
    const int lane  = tid & 31;
    const int half  = lane >> 4;           // half-warp -> token
    const int hl    = lane & 15;           // lane within half

    const int kv_len = lens[rb];
    const int start  = split * CHUNK;
    const int end    = min(start + CHUNK, kv_len);
    const int pbase  = ((r * NSPLIT + split) * BB + b) * HQ + hkv * GG;

    if (end <= start) {
        // Empty split: only mark the LSE; combine skips these entirely.
        if (tid < GG)
            g_plse[pbase + tid] = NEGINF;
        return;
    }

    __shared__ float4 s_s[TILE];      // scores [token][4 heads]
    __shared__ float4 p_s[TILE];      // probs  [token][4 heads]
    __shared__ int    pg_s[2][TILE];  // page per token (double-buffered)
    __shared__ float  sc_s[GG];       // per-head rescale for this tile
    __shared__ float  m_fin[GG], l_fin[GG];

    // Q into registers: head g, dims hl*8 .. hl*8+7
    const float* qb = q + (b * HQ + hkv * GG) * DD + hl * 8;
    float4 q0[GG], q1[GG];
    #pragma unroll
    for (int g = 0; g < GG; ++g) {
        q0[g] = *(const float4*)(qb + g * DD);
        q1[g] = *(const float4*)(qb + g * DD + 4);
    }

    const int*   btb = bt + rb * LL;
    const float* kh  = kc + (long)r * PP * HD + hkv * DD;
    const float* vh  = vc + (long)r * PP * HD + hkv * DD + tid;

    float acc0 = 0.f, acc1 = 0.f, acc2 = 0.f, acc3 = 0.f;
    float m_run = NEGINF, l_run = 0.f;   // warp-uniform state for head `wid`

    int buf = 0;
    for (int tb = start; tb < end; tb += TILE, buf ^= 1) {
        const int nt = min(TILE, end - tb);

        // ---- Phase A: scores. Half-warp per token, 8 tokens/CTA per pass.
        #pragma unroll
        for (int pass = 0; pass < 8; ++pass) {
            const int  tt    = pass * 8 + wid * 2 + half;
            const bool valid = (tt < nt);
            const int  page  = valid ? __ldg(btb + tb + tt) : 0;
            const float* kt  = kh + (long)page * HD + hl * 8;
            const float4 k0  = __ldcs((const float4*)kt);
            const float4 k1  = __ldcs((const float4*)(kt + 4));

            float s0 = q0[0].x*k0.x + q0[0].y*k0.y + q0[0].z*k0.z + q0[0].w*k0.w
                     + q1[0].x*k1.x + q1[0].y*k1.y + q1[0].z*k1.z + q1[0].w*k1.w;
            float s1 = q0[1].x*k0.x + q0[1].y*k0.y + q0[1].z*k0.z + q0[1].w*k0.w
                     + q1[1].x*k1.x + q1[1].y*k1.y + q1[1].z*k1.z + q1[1].w*k1.w;
            float s2 = q0[2].x*k0.x + q0[2].y*k0.y + q0[2].z*k0.z + q0[2].w*k0.w
                     + q1[2].x*k1.x + q1[2].y*k1.y + q1[2].z*k1.z + q1[2].w*k1.w;
            float s3 = q0[3].x*k0.x + q0[3].y*k0.y + q0[3].z*k0.z + q0[3].w*k0.w
                     + q1[3].x*k1.x + q1[3].y*k1.y + q1[3].z*k1.z + q1[3].w*k1.w;

            #pragma unroll
            for (int off = 8; off; off >>= 1) {
                s0 += __shfl_xor_sync(0xffffffffu, s0, off);
                s1 += __shfl_xor_sync(0xffffffffu, s1, off);
                s2 += __shfl_xor_sync(0xffffffffu, s2, off);
                s3 += __shfl_xor_sync(0xffffffffu, s3, off);
            }
            if (hl == 0) {
                s_s[tt] = valid ? make_float4(s0 * SCALE_F, s1 * SCALE_F,
                                              s2 * SCALE_F, s3 * SCALE_F)
                                : make_float4(NEGINF, NEGINF, NEGINF, NEGINF);
                pg_s[buf][tt] = page;
            }
        }
        __syncthreads();   // sync1: s_s / pg_s[buf] ready

        // ---- Online softmax: warp `wid` owns head `wid`, fully warp-local.
        {
            const float* sf = (const float*)s_s;
            const float  xa = sf[lane * 4 + wid];
            const float  xb = sf[(lane + 32) * 4 + wid];
            float x = fmaxf(xa, xb);
            #pragma unroll
            for (int off = 16; off; off >>= 1)
                x = fmaxf(x, __shfl_xor_sync(0xffffffffu, x, off));
            const float mo = m_run;
            const float mn = fmaxf(mo, x);
            const float scl = __expf(mo - mn);
            m_run = mn;
            if (lane == 0) sc_s[wid] = scl;
            const float pa = __expf(xa - mn);
            const float pb = __expf(xb - mn);
            float* pf = (float*)p_s;
            pf[lane * 4 + wid]        = pa;
            pf[(lane + 32) * 4 + wid] = pb;
            float ps = pa + pb;
            #pragma unroll
            for (int off = 16; off; off >>= 1)
                ps += __shfl_xor_sync(0xffffffffu, ps, off);
            l_run = l_run * scl + ps;
        }
        __syncthreads();   // sync2: p_s / sc_s ready

        // ---- Rescale + Phase B: thread tid owns dim d = tid for all 4 heads.
        const float c0 = sc_s[0], c1 = sc_s[1], c2 = sc_s[2], c3 = sc_s[3];
        acc0 *= c0; acc1 *= c1; acc2 *= c2; acc3 *= c3;

        #pragma unroll 8
        for (int j = 0; j < nt; ++j) {
            const float4 p4 = p_s[j];
            const float  v  = __ldcs(vh + (long)pg_s[buf][j] * HD);
            acc0 += p4.x * v; acc1 += p4.y * v;
            acc2 += p4.z * v; acc3 += p4.w * v;
        }
        // No barrier here: pg double-buffered; p_s/sc_s WAR protected by sync1
        // of the next iteration (writers pass it only after all warps leave B).
    }

    if (lane == 0) { m_fin[wid] = m_run; l_fin[wid] = l_run; }
    __syncthreads();

    const float l0 = fmaxf(l_fin[0], 1e-30f);
    const float l1 = fmaxf(l_fin[1], 1e-30f);
    const float l2 = fmaxf(l_fin[2], 1e-30f);
    const float l3 = fmaxf(l_fin[3], 1e-30f);
    g_po[(pbase + 0) * DD + tid] = acc0 / l0;
    g_po[(pbase + 1) * DD + tid] = acc1 / l1;
    g_po[(pbase + 2) * DD + tid] = acc2 / l2;
    g_po[(pbase + 3) * DD + tid] = acc3 / l3;
    if (tid < GG)
        g_plse[pbase + tid] = m_fin[tid] + __logf(fmaxf(l_fin[tid], 1e-30f));
}

__global__ void __launch_bounds__(128)
combine_kernel(float* __restrict__ out)
{
    const int bh   = blockIdx.x;    // b*HQ + hq
    const int d    = threadIdx.x;   // 0..127
    const int lane = d & 31;
    const int wid  = d >> 5;

    __shared__ float lse_s[RS];
    __shared__ int   idx_s[RS];
    __shared__ int   wcnt[4];

    lse_s[d] = g_plse[d * (BB * HQ) + bh];
    __syncthreads();

    float gm = NEGINF;
    #pragma unroll
    for (int i = 0; i < RS; ++i)
        gm = fmaxf(gm, lse_s[i]);

    // Deterministic compaction of non-empty partials (ballot + prefix).
    const bool flag = lse_s[d] > -5.0e29f;
    const unsigned mask = __ballot_sync(0xffffffffu, flag);
    const int pos = __popc(mask & ((1u << lane) - 1u));
    if (lane == 0) wcnt[wid] = __popc(mask);
    __syncthreads();
    int off = 0;
    #pragma unroll
    for (int w = 0; w < 4; ++w)
        if (w < wid) off += wcnt[w];
    if (flag) idx_s[off + pos] = d;
    const int nv = wcnt[0] + wcnt[1] + wcnt[2] + wcnt[3];
    __syncthreads();

    float acc = 0.f, ws = 0.f;
    #pragma unroll 4
    for (int t = 0; t < nv; ++t) {
        const int   i = idx_s[t];
        const float w = __expf(lse_s[i] - gm);
        ws  += w;
        acc += w * __ldg(&g_po[(i * (BB * HQ) + bh) * DD + d]);
    }
    out[bh * DD + d] = acc / fmaxf(ws, 1e-30f);
}

extern "C" void kernel_launch(void* const* d_in, const int* in_sizes, int n_in,
                              void* d_out, int out_size)
{
    (void)in_sizes; (void)n_in; (void)out_size;
    const float* q    = (const float*)d_in[0];
    const float* kc   = (const float*)d_in[1];
    const float* vc   = (const float*)d_in[2];
    const int*   lens = (const int*)d_in[3];
    const int*   bt   = (const int*)d_in[4];

    dim3 grid1(NSPLIT, HKV, RR * BB);
    decode_kernel<<<grid1, 128>>>(q, kc, vc, lens, bt);
    combine_kernel<<<BB * HQ, 128>>>((float*)d_out);
}